// round 3
// baseline (speedup 1.0000x reference)
#include <cuda_runtime.h>

#define HH 128
#define WW 128
#define BB 4
#define CIN 64
#define COUT 64
#define OC1 18

#define FFMA2(acc, a, b) asm("fma.rn.f32x2 %0, %1, %2, %0;" : "+l"(acc) : "l"(a), "l"(b))

// ---------------- scratch (no allocation allowed) ----------------
__device__ __align__(16) float g_xnhwc[BB*HH*WW*CIN];   // x in NHWC
__device__ __align__(16) float g_off9 [BB*HH*WW*9];     // raw conv1 out, channels 0..8
__device__ __align__(16) float g_wt1  [9*CIN*OC1];      // conv1 weights [tap][ci][oc]
__device__ __align__(16) float g_wt2  [9*CIN*COUT];     // conv2 weights [k][ci][co]
__device__ float g_stats1[BB*9*2];                      // GN1 sum/sumsq per (b,group)
__device__ float g_stats2[BB*16*2];                     // GN2 sum/sumsq per (b,group)
__device__ float g_sc1[BB*9],  g_sh1[BB*9];             // GN1 per-channel scale/shift
__device__ float g_sc2[BB*COUT], g_sh2[BB*COUT];        // GN2 per-channel scale/shift

// ---------------- K: zero stats ----------------
__global__ void k_zero_stats() {
    int t = threadIdx.x;
    if (t < BB*9*2)  g_stats1[t] = 0.f;
    if (t < BB*16*2) g_stats2[t] = 0.f;
}

// ---------------- K: transpose x NCHW -> NHWC ----------------
__global__ void k_transpose_x(const float* __restrict__ x) {
    __shared__ float tile[32][33];
    int b  = blockIdx.z;
    int p0 = blockIdx.x * 32;          // pixel (h*W+w) tile
    int c0 = blockIdx.y * 32;          // channel tile
    int tx = threadIdx.x, ty = threadIdx.y;   // 32 x 8
    const float* xb = x + (size_t)b*CIN*HH*WW;
    #pragma unroll
    for (int i = 0; i < 32; i += 8)
        tile[ty+i][tx] = xb[(c0+ty+i)*(HH*WW) + p0 + tx];
    __syncthreads();
    float* ob = g_xnhwc + (size_t)b*HH*WW*CIN;
    #pragma unroll
    for (int i = 0; i < 32; i += 8)
        ob[(size_t)(p0+ty+i)*CIN + c0 + tx] = tile[tx][ty+i];
}

// ---------------- K: transpose weights ----------------
__global__ void k_prep_w(const float* __restrict__ w_off, const float* __restrict__ w_dsc) {
    int t = blockIdx.x*blockDim.x + threadIdx.x;
    if (t < 9*CIN*OC1) {
        int tap = t / (CIN*OC1); int r = t % (CIN*OC1);
        int ci = r / OC1; int oc = r % OC1;
        g_wt1[t] = w_off[oc*(CIN*9) + ci*9 + tap];     // w_off (18,64,3,3)
    }
    if (t < 9*CIN*COUT) {
        int k = t / (CIN*COUT); int r = t % (CIN*COUT);
        int ci = r / COUT; int co = r % COUT;
        g_wt2[t] = w_dsc[co*(CIN*9) + ci*9 + k];       // w_dsc (64,64,9,1)
    }
}

// ---------------- K: conv1 3x3 (64->18) + GN1 stats, packed f32x2 ----------------
// grid: B*H*2 (64-px half-rows), 96 threads: tx(0..31)->2px, ty(0..2)->6oc(3 pairs)
__global__ __launch_bounds__(96) void k_conv1(const float* __restrict__ b_off) {
    __shared__ __align__(16) float2 xs2[CIN*68];     // [ci][66]: idx i <-> w = w0+i-1, duplicated
    __shared__ __align__(16) float  ws [3*CIN*OC1];  // [dx][ci][18]
    __shared__ float ssum[9], ssq[9];
    int t = threadIdx.x;
    int tx = t & 31, ty = t >> 5;
    int blk  = blockIdx.x;
    int half = blk & 1;
    int h    = (blk >> 1) & (HH-1);
    int b    = blk >> 8;
    int w0   = half * 64;
    if (t < 9) { ssum[t] = 0.f; ssq[t] = 0.f; }

    unsigned long long acc[2][3];
    #pragma unroll
    for (int p=0;p<2;p++)
        #pragma unroll
        for (int j=0;j<3;j++) acc[p][j]=0ull;

    const float* xb = g_xnhwc + (size_t)b*(HH*WW*CIN);

    for (int dy = 0; dy < 3; dy++) {
        int y = h + dy - 1;
        __syncthreads();
        // stage one input row (66 positions x 64 ci), zero-padded, duplicated pairs
        for (int idx = t; idx < 66*16; idx += 96) {
            int pp = idx >> 4;       // 0..65, stored at idx pp: w = w0+pp-1
            int q  = idx & 15;       // float4 group of ci
            int w  = w0 + pp - 1;
            float4 v = make_float4(0.f,0.f,0.f,0.f);
            if ((unsigned)y < HH && (unsigned)w < WW)
                v = *(const float4*)(xb + ((size_t)y*WW + w)*CIN + q*4);
            xs2[(q*4+0)*68 + pp] = make_float2(v.x, v.x);
            xs2[(q*4+1)*68 + pp] = make_float2(v.y, v.y);
            xs2[(q*4+2)*68 + pp] = make_float2(v.z, v.z);
            xs2[(q*4+3)*68 + pp] = make_float2(v.w, v.w);
        }
        // stage weights for the 3 taps of this dy: contiguous [dx][ci][18]
        {
            const float4* wsrc = (const float4*)(g_wt1 + dy*3*CIN*OC1);
            float4* wdst = (float4*)ws;
            for (int idx = t; idx < 3*CIN*OC1/4; idx += 96) wdst[idx] = wsrc[idx];
        }
        __syncthreads();
        #pragma unroll 2
        for (int ci = 0; ci < CIN; ci++) {
            // xr[j] = idx 2tx+j  <->  input w = w0 + 2tx + j - 1
            // output px p=2tx+pp needs input idx p+dx for tap dx
            const float2* xr = xs2 + ci*68 + 2*tx;              // 16B aligned
            ulonglong2 q01 = *(const ulonglong2*)(xr);
            ulonglong2 q23 = *(const ulonglong2*)(xr + 2);
            #pragma unroll
            for (int dx = 0; dx < 3; dx++) {
                const unsigned long long* wp =
                    (const unsigned long long*)(ws + (dx*CIN + ci)*OC1 + 6*ty);
                unsigned long long b0 = wp[0], b1 = wp[1], b2 = wp[2];
                unsigned long long a0 = (dx==0) ? q01.x : (dx==1) ? q01.y : q23.x;
                unsigned long long a1 = (dx==0) ? q01.y : (dx==1) ? q23.x : q23.y;
                FFMA2(acc[0][0], a0, b0); FFMA2(acc[0][1], a0, b1); FFMA2(acc[0][2], a0, b2);
                FFMA2(acc[1][0], a1, b0); FFMA2(acc[1][1], a1, b1); FFMA2(acc[1][2], a1, b2);
            }
        }
    }
    __syncthreads();
    // epilogue: bias, store first 9 channels, GN1 stats (pair j == group ty*3+j)
    union UF2 { unsigned long long u; float2 f; };
    #pragma unroll
    for (int j = 0; j < 3; j++) {
        int oc = ty*6 + 2*j;
        float bv0 = b_off[oc], bv1 = b_off[oc+1];
        float s = 0.f, sq = 0.f;
        #pragma unroll
        for (int p = 0; p < 2; p++) {
            UF2 u; u.u = acc[p][j];
            float r0 = u.f.x + bv0;
            float r1 = u.f.y + bv1;
            s += r0 + r1; sq += r0*r0 + r1*r1;
            int w = w0 + 2*tx + p;
            size_t base = (((size_t)b*HH + h)*WW + w)*9;
            if (oc < 9)     g_off9[base + oc]     = r0;
            if (oc + 1 < 9) g_off9[base + oc + 1] = r1;
        }
        atomicAdd(&ssum[ty*3+j], s);
        atomicAdd(&ssq [ty*3+j], sq);
    }
    __syncthreads();
    if (t < 9) {
        atomicAdd(&g_stats1[(b*9 + t)*2 + 0], ssum[t]);
        atomicAdd(&g_stats1[(b*9 + t)*2 + 1], ssq[t]);
    }
}

// ---------------- K: finalize GN1 ----------------
__global__ void k_finalize1(const float* __restrict__ g_gn_off, const float* __restrict__ b_gn_off) {
    int t = threadIdx.x;
    if (t >= BB*9) return;
    int b = t / 9, c = t % 9, g = c >> 1;
    float N  = 2.f*HH*WW;
    float mu = g_stats1[(b*9+g)*2+0] / N;
    float var= g_stats1[(b*9+g)*2+1] / N - mu*mu;
    float inv= rsqrtf(var + 1e-5f);
    float sc = g_gn_off[c] * inv;
    g_sc1[t] = sc;
    g_sh1[t] = b_gn_off[c] - mu * sc;
}

// ---------------- K: main fused, packed f32x2 GEMM ----------------
// grid: B*H*2 (64-px half-rows), 256 threads: tx(0..7)->8co, ty(0..31)->2px
// dynamic smem: s2 (dup samples, 32KB) | Wc (16KB) | cyc (2304B) | sgrp (128B)
#define SM_S2   0
#define SM_WC   32768
#define SM_CYC  49152
#define SM_GRP  51456
#define SM_MAIN 51584

__global__ __launch_bounds__(256, 4) void k_main(const float* __restrict__ b_dsc, float* __restrict__ out) {
    extern __shared__ __align__(16) char smem_raw[];
    float* s2   = (float*)(smem_raw + SM_S2);     // [ci][px] as float2 dup
    float* Wc   = (float*)(smem_raw + SM_WC);     // [ci][co]
    float* cyc  = (float*)(smem_raw + SM_CYC);    // clipped y coord per (k,px)
    float* sgrp = (float*)(smem_raw + SM_GRP);

    int t    = threadIdx.x;
    int blk  = blockIdx.x;
    int half = blk & 1;
    int h    = (blk >> 1) & (HH-1);
    int b    = blk >> 8;
    int w0   = half * 64;

    if (t < 32) sgrp[t] = 0.f;

    // ---- prologue: per-pixel offsets -> tanh -> cumsum -> clipped y coords ----
    if (t < 64) {
        int px = t;
        int w  = w0 + px;
        const float* op = g_off9 + (((size_t)b*HH + h)*WW + w)*9;
        float y[9];
        #pragma unroll
        for (int c = 0; c < 9; c++)
            y[c] = tanhf(op[c]*g_sc1[b*9+c] + g_sh1[b*9+c]);
        float o[9];
        o[4]=0.f;
        o[3]=y[3]; o[2]=y[2]+o[3]; o[1]=y[1]+o[2]; o[0]=y[0]+o[1];
        o[5]=y[5]; o[6]=o[5]+y[6]; o[7]=o[6]+y[7]; o[8]=o[7]+y[8];
        #pragma unroll
        for (int k = 0; k < 9; k++)
            cyc[k*64+px] = fminf(fmaxf((float)h + o[k], 0.f), (float)(HH-1));
    }

    int tx = t & 7,  ty = t >> 3;     // co0 = 8*tx, px0 = 2*ty
    unsigned long long acc[2][4];
    #pragma unroll
    for (int p=0;p<2;p++)
        #pragma unroll
        for (int j=0;j<4;j++) acc[p][j]=0ull;

    int spx = t >> 2;            // sampling: one px per 4 threads
    int c4  = (t & 3) * 16;      // each thread: 16 channels
    const float* xb = g_xnhwc + (size_t)b*(HH*WW*CIN);

    for (int k = 0; k < 9; k++) {
        __syncthreads();
        // stage weight chunk [64ci][64co]
        {
            const float4* wsrc = (const float4*)(g_wt2 + k*CIN*COUT);
            float4* wdst = (float4*)Wc;
            #pragma unroll
            for (int i = 0; i < 4; i++)
                wdst[t + i*256] = wsrc[t + i*256];
        }
        // build sample chunk: vertical 2-point lerp (x-coord exact integer), duplicated
        {
            int w  = w0 + spx;
            int x0 = min(max(w + k - 4, 0), WW-1);
            float ycv = cyc[k*64 + spx];
            float y0f = floorf(ycv);
            float wy  = ycv - y0f;
            int y0 = (int)y0f;
            int y1 = min(y0 + 1, HH-1);
            const float* p0 = xb + ((size_t)y0*WW + x0)*CIN + c4;
            const float* p1 = xb + ((size_t)y1*WW + x0)*CIN + c4;
            float2* sp = (float2*)s2;
            #pragma unroll
            for (int q = 0; q < 4; q++) {
                float4 v0 = *(const float4*)(p0 + q*4);
                float4 v1 = *(const float4*)(p1 + q*4);
                int ci = c4 + q*4;
                float r0 = v0.x + wy*(v1.x - v0.x);
                float r1 = v0.y + wy*(v1.y - v0.y);
                float r2 = v0.z + wy*(v1.z - v0.z);
                float r3 = v0.w + wy*(v1.w - v0.w);
                sp[(ci+0)*64 + spx] = make_float2(r0, r0);
                sp[(ci+1)*64 + spx] = make_float2(r1, r1);
                sp[(ci+2)*64 + spx] = make_float2(r2, r2);
                sp[(ci+3)*64 + spx] = make_float2(r3, r3);
            }
        }
        __syncthreads();
        // packed GEMM accumulate: per ci 3 LDS + 8 FFMA2 = 32 flops
        #pragma unroll 2
        for (int ci = 0; ci < CIN; ci++) {
            ulonglong2 av  = *(const ulonglong2*)(s2 + ci*128 + ty*4);        // 2 px dup-pairs
            ulonglong2 b01 = *(const ulonglong2*)(Wc + ci*64 + tx*8);         // co pairs 0,1
            ulonglong2 b23 = *(const ulonglong2*)(Wc + ci*64 + tx*8 + 4);     // co pairs 2,3
            FFMA2(acc[0][0], av.x, b01.x); FFMA2(acc[0][1], av.x, b01.y);
            FFMA2(acc[0][2], av.x, b23.x); FFMA2(acc[0][3], av.x, b23.y);
            FFMA2(acc[1][0], av.y, b01.x); FFMA2(acc[1][1], av.y, b01.y);
            FFMA2(acc[1][2], av.y, b23.x); FFMA2(acc[1][3], av.y, b23.y);
        }
    }
    // epilogue: bias, float2 stores (contiguous w), GN2 stats
    union UF2 { unsigned long long u; float2 f; };
    int co0 = tx*8;
    float gs[2] = {0.f, 0.f}, gq[2] = {0.f, 0.f};
    #pragma unroll
    for (int j = 0; j < 4; j++) {
        UF2 u0; u0.u = acc[0][j];
        UF2 u1; u1.u = acc[1][j];
        int ce = co0 + 2*j, cogrp = j >> 1;
        float be = b_dsc[ce], bo = b_dsc[ce+1];
        float2 ste = make_float2(u0.f.x + be, u1.f.x + be);   // co=ce, px0/px0+1
        float2 sto = make_float2(u0.f.y + bo, u1.f.y + bo);   // co=ce+1
        *(float2*)&out[(((size_t)b*COUT + ce  )*HH + h)*WW + w0 + 2*ty] = ste;
        *(float2*)&out[(((size_t)b*COUT + ce+1)*HH + h)*WW + w0 + 2*ty] = sto;
        gs[cogrp] += ste.x + ste.y + sto.x + sto.y;
        gq[cogrp] += ste.x*ste.x + ste.y*ste.y + sto.x*sto.x + sto.y*sto.y;
    }
    atomicAdd(&sgrp[(tx*2+0)*2+0], gs[0]);
    atomicAdd(&sgrp[(tx*2+0)*2+1], gq[0]);
    atomicAdd(&sgrp[(tx*2+1)*2+0], gs[1]);
    atomicAdd(&sgrp[(tx*2+1)*2+1], gq[1]);
    __syncthreads();
    if (t < 32) atomicAdd(&g_stats2[b*32 + t], sgrp[t]);
}

// ---------------- K: finalize GN2 ----------------
__global__ void k_finalize2(const float* __restrict__ g_gn, const float* __restrict__ b_gn) {
    int t = threadIdx.x;
    if (t >= BB*COUT) return;
    int b = t >> 6, co = t & 63, g = co >> 2;
    float N  = 4.f*HH*WW;
    float mu = g_stats2[(b*16+g)*2+0] / N;
    float var= g_stats2[(b*16+g)*2+1] / N - mu*mu;
    float inv= rsqrtf(var + 1e-5f);
    float sc = g_gn[co] * inv;
    g_sc2[t] = sc;
    g_sh2[t] = b_gn[co] - mu * sc;
}

// ---------------- K: normalize + relu in place ----------------
__global__ void k_norm_relu(float* __restrict__ out) {
    int idx = blockIdx.x*blockDim.x + threadIdx.x;   // float4 index
    int e  = idx << 2;
    int bc = e >> 14;                                 // b*64+co
    float sc = g_sc2[bc], sh = g_sh2[bc];
    float4 v = ((float4*)out)[idx];
    v.x = fmaxf(v.x*sc + sh, 0.f);
    v.y = fmaxf(v.y*sc + sh, 0.f);
    v.z = fmaxf(v.z*sc + sh, 0.f);
    v.w = fmaxf(v.w*sc + sh, 0.f);
    ((float4*)out)[idx] = v;
}

// ---------------- launch ----------------
extern "C" void kernel_launch(void* const* d_in, const int* in_sizes, int n_in,
                              void* d_out, int out_size) {
    const float* x        = (const float*)d_in[0];
    const float* w_off    = (const float*)d_in[1];
    const float* b_off    = (const float*)d_in[2];
    const float* g_gn_off = (const float*)d_in[3];
    const float* b_gn_off = (const float*)d_in[4];
    const float* w_dsc    = (const float*)d_in[5];
    const float* b_dsc    = (const float*)d_in[6];
    const float* g_gn     = (const float*)d_in[7];
    const float* b_gn     = (const float*)d_in[8];
    float* out = (float*)d_out;

    cudaFuncSetAttribute(k_main, cudaFuncAttributeMaxDynamicSharedMemorySize, SM_MAIN);

    k_zero_stats<<<1,128>>>();
    k_transpose_x<<<dim3(512,2,4), dim3(32,8)>>>(x);
    k_prep_w<<<144,256>>>(w_off, w_dsc);
    k_conv1<<<BB*HH*2, 96>>>(b_off);
    k_finalize1<<<1,64>>>(g_gn_off, b_gn_off);
    k_main<<<BB*HH*2, 256, SM_MAIN>>>(b_dsc, out);
    k_finalize2<<<1,256>>>(g_gn, b_gn);
    k_norm_relu<<<4096,256>>>(out);
}

// round 5
// speedup vs baseline: 1.3954x; 1.3954x over previous
#include <cuda_runtime.h>
#include <cstdint>

#define HH 128
#define WW 128
#define BB 4
#define CIN 64
#define COUT 64
#define OC1 18

// ---------------- scratch (no allocation allowed) ----------------
__device__ __align__(16) float g_xnhwc[BB*HH*WW*CIN];   // x in NHWC
__device__ __align__(16) float g_off9 [BB*HH*WW*9];     // raw conv1 out, channels 0..8
__device__ __align__(16) float g_wt1  [9*CIN*OC1];      // conv1 weights [tap][ci][oc]
__device__ __align__(16) float g_wt2  [9*COUT*CIN];     // conv2 weights [k][co][ci], tf32-rounded
__device__ float g_stats1[BB*9*2];
__device__ float g_stats2[BB*16*2];
__device__ float g_sc1[BB*9],  g_sh1[BB*9];
__device__ float g_sc2[BB*COUT], g_sh2[BB*COUT];

__device__ __forceinline__ uint32_t f2tf32(float v) {
    uint32_t r;
    asm("cvt.rna.tf32.f32 %0, %1;" : "=r"(r) : "f"(v));
    return r;
}

#define MMA_TF32(c, a0,a1,a2,a3, b0,b1) \
    asm volatile("mma.sync.aligned.m16n8k8.row.col.f32.tf32.tf32.f32 " \
        "{%0,%1,%2,%3}, {%4,%5,%6,%7}, {%8,%9}, {%0,%1,%2,%3};" \
        : "+f"((c)[0]),"+f"((c)[1]),"+f"((c)[2]),"+f"((c)[3]) \
        : "r"(a0),"r"(a1),"r"(a2),"r"(a3),"r"(b0),"r"(b1))

// ---------------- K: zero stats ----------------
__global__ void k_zero_stats() {
    int t = threadIdx.x;
    if (t < BB*9*2)  g_stats1[t] = 0.f;
    if (t < BB*16*2) g_stats2[t] = 0.f;
}

// ---------------- K: transpose x NCHW -> NHWC ----------------
__global__ void k_transpose_x(const float* __restrict__ x) {
    __shared__ float tile[32][33];
    int b  = blockIdx.z;
    int p0 = blockIdx.x * 32;
    int c0 = blockIdx.y * 32;
    int tx = threadIdx.x, ty = threadIdx.y;   // 32 x 8
    const float* xb = x + (size_t)b*CIN*HH*WW;
    #pragma unroll
    for (int i = 0; i < 32; i += 8)
        tile[ty+i][tx] = xb[(c0+ty+i)*(HH*WW) + p0 + tx];
    __syncthreads();
    float* ob = g_xnhwc + (size_t)b*HH*WW*CIN;
    #pragma unroll
    for (int i = 0; i < 32; i += 8)
        ob[(size_t)(p0+ty+i)*CIN + c0 + tx] = tile[tx][ty+i];
}

// ---------------- K: transpose weights (wt2 tf32-rounded) ----------------
__global__ void k_prep_w(const float* __restrict__ w_off, const float* __restrict__ w_dsc) {
    int t = blockIdx.x*blockDim.x + threadIdx.x;
    if (t < 9*CIN*OC1) {
        int tap = t / (CIN*OC1); int r = t % (CIN*OC1);
        int ci = r / OC1; int oc = r % OC1;
        g_wt1[t] = w_off[oc*(CIN*9) + ci*9 + tap];     // w_off (18,64,3,3)
    }
    if (t < 9*COUT*CIN) {
        int k = t / (COUT*CIN); int r = t % (COUT*CIN);
        int co = r / CIN; int ci = r % CIN;
        float v = w_dsc[co*(CIN*9) + ci*9 + k];        // w_dsc (64,64,9,1)
        g_wt2[t] = __uint_as_float(f2tf32(v));
    }
}

// ---------------- K: conv1 3x3 (64->18) + GN1 stats (verified scalar) ----------------
__global__ __launch_bounds__(96) void k_conv1(const float* __restrict__ b_off) {
    __shared__ __align__(16) float xs[CIN*68];
    __shared__ __align__(16) float ws[3*CIN*OC1];
    __shared__ float ssum[9], ssq[9];
    int t = threadIdx.x;
    int tx = t & 15, ty = t >> 4;
    int blk  = blockIdx.x;
    int half = blk & 1;
    int h    = (blk >> 1) & (HH-1);
    int b    = blk >> 8;
    int w0   = half * 64;
    if (t < 9) { ssum[t] = 0.f; ssq[t] = 0.f; }

    float acc[4][3];
    #pragma unroll
    for (int i=0;i<4;i++)
        #pragma unroll
        for (int j=0;j<3;j++) acc[i][j]=0.f;

    const float* xb = g_xnhwc + (size_t)b*(HH*WW*CIN);

    for (int dy = 0; dy < 3; dy++) {
        int y = h + dy - 1;
        __syncthreads();
        for (int idx = t; idx < 66*16; idx += 96) {
            int pp = idx >> 4;
            int q  = idx & 15;
            int w  = w0 + pp - 1;
            float4 v = make_float4(0.f,0.f,0.f,0.f);
            if ((unsigned)y < HH && (unsigned)w < WW)
                v = *(const float4*)(xb + ((size_t)y*WW + w)*CIN + q*4);
            xs[(q*4+0)*68 + pp] = v.x;
            xs[(q*4+1)*68 + pp] = v.y;
            xs[(q*4+2)*68 + pp] = v.z;
            xs[(q*4+3)*68 + pp] = v.w;
        }
        const float* wsrc = g_wt1 + dy*3*CIN*OC1;
        for (int idx = t; idx < 3*CIN*OC1; idx += 96) ws[idx] = wsrc[idx];
        __syncthreads();
        #pragma unroll
        for (int dx = 0; dx < 3; dx++) {
            const float* wd = ws + dx*CIN*OC1 + ty*3;
            #pragma unroll 4
            for (int ci = 0; ci < CIN; ci++) {
                const float* xr = xs + ci*68 + tx*4 + dx;
                float a0 = xr[0], a1 = xr[1], a2 = xr[2], a3 = xr[3];
                float b0 = wd[ci*OC1+0], b1 = wd[ci*OC1+1], b2 = wd[ci*OC1+2];
                acc[0][0]+=a0*b0; acc[0][1]+=a0*b1; acc[0][2]+=a0*b2;
                acc[1][0]+=a1*b0; acc[1][1]+=a1*b1; acc[1][2]+=a1*b2;
                acc[2][0]+=a2*b0; acc[2][1]+=a2*b1; acc[2][2]+=a2*b2;
                acc[3][0]+=a3*b0; acc[3][1]+=a3*b1; acc[3][2]+=a3*b2;
            }
        }
    }
    __syncthreads();
    #pragma unroll
    for (int j = 0; j < 3; j++) {
        int oc = ty*3 + j;
        float bia = b_off[oc];
        float s = 0.f, sq = 0.f;
        #pragma unroll
        for (int i = 0; i < 4; i++) {
            float r = acc[i][j] + bia;
            s += r; sq += r*r;
            if (oc < 9)
                g_off9[(((size_t)b*HH + h)*WW + (w0 + tx*4 + i))*9 + oc] = r;
        }
        atomicAdd(&ssum[oc>>1], s);
        atomicAdd(&ssq [oc>>1], sq);
    }
    __syncthreads();
    if (t < 9) {
        atomicAdd(&g_stats1[(b*9 + t)*2 + 0], ssum[t]);
        atomicAdd(&g_stats1[(b*9 + t)*2 + 1], ssq[t]);
    }
}

// ---------------- K: finalize GN1 ----------------
__global__ void k_finalize1(const float* __restrict__ g_gn_off, const float* __restrict__ b_gn_off) {
    int t = threadIdx.x;
    if (t >= BB*9) return;
    int b = t / 9, c = t % 9, g = c >> 1;
    float N  = 2.f*HH*WW;
    float mu = g_stats1[(b*9+g)*2+0] / N;
    float var= g_stats1[(b*9+g)*2+1] / N - mu*mu;
    float inv= rsqrtf(var + 1e-5f);
    float sc = g_gn_off[c] * inv;
    g_sc1[t] = sc;
    g_sh1[t] = b_gn_off[c] - mu * sc;
}

// ---------------- K: main fused via mma.sync tf32 ----------------
// Block = one image row: M=128 px, N=64 co, K=576 (9 taps x 64 ci).
// 256 threads = 8 warps; warp w -> px rows [w*16, w*16+16), all 64 co.
// smem (dynamic):
//   As: A fragments packed [kb(8)][c4(4)][pxg(64)] float4
//       float4 = (A[px][kb*8+c4], A[px+8][..], A[px][kb*8+c4+4], A[px+8][..+4]),
//       pxg = (px>>4)*8 + (px&7)  (px&8 selects .y/.w lanes)
//   Bs: B fragments packed [kb(8)][kk(4)][np(4)][n_in(8)] float4
//       float4 = (B[k][n], B[k+4][n], B[k][n+8], B[k+4][n+8]),
//       k = kb*8+kk, n = np*16+n_in (tiles np*16 and np*16+8)
#define SM_AS   0
#define SM_BS   32768
#define SM_CYC  49152
#define SM_GRP  53760
#define SM_MAIN 53888

__global__ __launch_bounds__(256) void k_main(const float* __restrict__ b_dsc, float* __restrict__ out) {
    extern __shared__ __align__(16) char smem[];
    float*  As   = (float*)(smem + SM_AS);
    float*  Bs   = (float*)(smem + SM_BS);
    uint4*  As4  = (uint4*)As;
    uint4*  Bs4  = (uint4*)Bs;
    float*  cyc  = (float*)(smem + SM_CYC);
    float*  sgrp = (float*)(smem + SM_GRP);

    int t   = threadIdx.x;
    int blk = blockIdx.x;
    int h   = blk & (HH-1);
    int b   = blk >> 7;

    if (t < 32) sgrp[t] = 0.f;

    // prologue: per-pixel offsets -> tanh -> cumsum -> clipped y coords
    if (t < 128) {
        int px = t;
        const float* op = g_off9 + (((size_t)b*HH + h)*WW + px)*9;
        float y[9];
        #pragma unroll
        for (int c = 0; c < 9; c++)
            y[c] = tanhf(op[c]*g_sc1[b*9+c] + g_sh1[b*9+c]);
        float o[9];
        o[4]=0.f;
        o[3]=y[3]; o[2]=y[2]+o[3]; o[1]=y[1]+o[2]; o[0]=y[0]+o[1];
        o[5]=y[5]; o[6]=o[5]+y[6]; o[7]=o[6]+y[7]; o[8]=o[7]+y[8];
        #pragma unroll
        for (int k = 0; k < 9; k++)
            cyc[k*128+px] = fminf(fmaxf((float)h + o[k], 0.f), (float)(HH-1));
    }

    const float* xb = g_xnhwc + (size_t)b*(HH*WW*CIN);

    // A-fill mapping: px = t>>1, 32 ci per thread
    int apx  = t >> 1;
    int aci0 = (t & 1) * 32;
    int apxg4 = (((apx >> 4) << 3) | (apx & 7)) * 4;   // pxg*4 floats
    int apbit = (apx >> 3) & 1;
    // B-fill mapping: co = t>>2, 16 ci per thread
    int bco  = t >> 2;
    int bci0 = (t & 3) * 16;
    int bnoff = (bco >> 4)*32 + (bco & 7)*4 + ((bco >> 3) & 1)*2;   // float offset from kk-row

    int lane = t & 31;
    int m0   = (t >> 5) * 16;
    float acc[8][4];   // [np*2+half][4]
    #pragma unroll
    for (int i = 0; i < 8; i++)
        #pragma unroll
        for (int j = 0; j < 4; j++) acc[i][j] = 0.f;

    int aridx = (lane & 3) * 64 + (m0 >> 4)*8 + (lane >> 2);   // + kb*256 (float4)
    int bridx = (lane & 3) * 32 + (lane >> 2);                 // + kb*128 + np*8 (float4)

    for (int k = 0; k < 9; k++) {
        __syncthreads();   // previous tap's LDS reads done -> safe to overwrite
        // ---- fill A: bilinear samples (x exact integer -> vertical lerp), tf32 ----
        {
            int x0 = min(max(apx + k - 4, 0), WW-1);
            float ycv = cyc[k*128 + apx];
            float y0f = floorf(ycv);
            float wy  = ycv - y0f;
            int y0 = (int)y0f;
            int y1 = min(y0 + 1, HH-1);
            const float* p0 = xb + ((size_t)y0*WW + x0)*CIN + aci0;
            const float* p1 = xb + ((size_t)y1*WW + x0)*CIN + aci0;
            #pragma unroll
            for (int q = 0; q < 8; q++) {
                float4 v0 = *(const float4*)(p0 + q*4);
                float4 v1 = *(const float4*)(p1 + q*4);
                float r[4];
                r[0] = v0.x + wy*(v1.x - v0.x);
                r[1] = v0.y + wy*(v1.y - v0.y);
                r[2] = v0.z + wy*(v1.z - v0.z);
                r[3] = v0.w + wy*(v1.w - v0.w);
                #pragma unroll
                for (int j = 0; j < 4; j++) {
                    int ci = aci0 + q*4 + j;
                    int fa = ((ci >> 3)*4 + (ci & 3))*256 + apxg4 + ((ci >> 2) & 1)*2 + apbit;
                    As[fa] = __uint_as_float(f2tf32(r[j]));
                }
            }
        }
        // ---- fill B: tap weights (already tf32-rounded) ----
        {
            const float* wsrc = g_wt2 + k*(COUT*CIN) + bco*CIN + bci0;
            #pragma unroll
            for (int q = 0; q < 4; q++) {
                float4 v = *(const float4*)(wsrc + q*4);
                float r[4] = {v.x, v.y, v.z, v.w};
                #pragma unroll
                for (int j = 0; j < 4; j++) {
                    int ci = bci0 + q*4 + j;
                    int fb = ((ci >> 3)*4 + (ci & 3))*128 + bnoff + ((ci >> 2) & 1);
                    Bs[fb] = r[j];
                }
            }
        }
        __syncthreads();
        // ---- MMA: 8 k-steps x 8 n-tiles ----
        #pragma unroll
        for (int kb = 0; kb < 8; kb++) {
            uint4 av = As4[kb*256 + aridx];
            #pragma unroll
            for (int np = 0; np < 4; np++) {
                uint4 bv = Bs4[kb*128 + np*8 + bridx];
                MMA_TF32(acc[np*2+0], av.x, av.y, av.z, av.w, bv.x, bv.y);
                MMA_TF32(acc[np*2+1], av.x, av.y, av.z, av.w, bv.z, bv.w);
            }
        }
    }

    // epilogue: bias, NCHW stores, GN2 stats
    int r0 = m0 + (lane >> 2);
    #pragma unroll
    for (int np = 0; np < 4; np++) {
        #pragma unroll
        for (int half = 0; half < 2; half++) {
            float* a4 = acc[np*2+half];
            int co0 = np*16 + half*8 + (lane & 3)*2;
            float bi0 = b_dsc[co0], bi1 = b_dsc[co0+1];
            float v00 = a4[0] + bi0, v01 = a4[1] + bi1;
            float v10 = a4[2] + bi0, v11 = a4[3] + bi1;
            out[((size_t)(b*COUT + co0  )*HH + h)*WW + r0    ] = v00;
            out[((size_t)(b*COUT + co0+1)*HH + h)*WW + r0    ] = v01;
            out[((size_t)(b*COUT + co0  )*HH + h)*WW + r0 + 8] = v10;
            out[((size_t)(b*COUT + co0+1)*HH + h)*WW + r0 + 8] = v11;
            float s  = v00 + v01 + v10 + v11;
            float sq = v00*v00 + v01*v01 + v10*v10 + v11*v11;
            #pragma unroll
            for (int m = 16; m >= 1; m >>= (m==4)?2:1) {   // masks 16,8,4,1
                s  += __shfl_xor_sync(0xFFFFFFFFu, s,  m);
                sq += __shfl_xor_sync(0xFFFFFFFFu, sq, m);
                if (m == 1) break;
            }
            if (lane == 0 || lane == 2) {
                int g = np*4 + half*2 + (lane >> 1);
                atomicAdd(&sgrp[g*2+0], s);
                atomicAdd(&sgrp[g*2+1], sq);
            }
        }
    }
    __syncthreads();
    if (t < 32) atomicAdd(&g_stats2[b*32 + t], sgrp[t]);
}

// ---------------- K: finalize GN2 ----------------
__global__ void k_finalize2(const float* __restrict__ g_gn, const float* __restrict__ b_gn) {
    int t = threadIdx.x;
    if (t >= BB*COUT) return;
    int b = t >> 6, co = t & 63, g = co >> 2;
    float N  = 4.f*HH*WW;
    float mu = g_stats2[(b*16+g)*2+0] / N;
    float var= g_stats2[(b*16+g)*2+1] / N - mu*mu;
    float inv= rsqrtf(var + 1e-5f);
    float sc = g_gn[co] * inv;
    g_sc2[t] = sc;
    g_sh2[t] = b_gn[co] - mu * sc;
}

// ---------------- K: normalize + relu in place ----------------
__global__ void k_norm_relu(float* __restrict__ out) {
    int idx = blockIdx.x*blockDim.x + threadIdx.x;
    int e  = idx << 2;
    int bc = e >> 14;
    float sc = g_sc2[bc], sh = g_sh2[bc];
    float4 v = ((float4*)out)[idx];
    v.x = fmaxf(v.x*sc + sh, 0.f);
    v.y = fmaxf(v.y*sc + sh, 0.f);
    v.z = fmaxf(v.z*sc + sh, 0.f);
    v.w = fmaxf(v.w*sc + sh, 0.f);
    ((float4*)out)[idx] = v;
}

// ---------------- launch ----------------
extern "C" void kernel_launch(void* const* d_in, const int* in_sizes, int n_in,
                              void* d_out, int out_size) {
    const float* x        = (const float*)d_in[0];
    const float* w_off    = (const float*)d_in[1];
    const float* b_off    = (const float*)d_in[2];
    const float* g_gn_off = (const float*)d_in[3];
    const float* b_gn_off = (const float*)d_in[4];
    const float* w_dsc    = (const float*)d_in[5];
    const float* b_dsc    = (const float*)d_in[6];
    const float* g_gn     = (const float*)d_in[7];
    const float* b_gn     = (const float*)d_in[8];
    float* out = (float*)d_out;

    cudaFuncSetAttribute(k_main, cudaFuncAttributeMaxDynamicSharedMemorySize, SM_MAIN);

    k_zero_stats<<<1,128>>>();
    k_transpose_x<<<dim3(512,2,4), dim3(32,8)>>>(x);
    k_prep_w<<<144,256>>>(w_off, w_dsc);
    k_conv1<<<BB*HH*2, 96>>>(b_off);
    k_finalize1<<<1,64>>>(g_gn_off, b_gn_off);
    k_main<<<BB*HH, 256, SM_MAIN>>>(b_dsc, out);
    k_finalize2<<<1,256>>>(g_gn, b_gn);
    k_norm_relu<<<4096,256>>>(out);
}

// round 6
// speedup vs baseline: 1.9381x; 1.3889x over previous
#include <cuda_runtime.h>

#define HH 128
#define WW 128
#define BB 4
#define CIN 64
#define COUT 64
#define OC1 18

// ---------------- scratch (no allocation allowed) ----------------
__device__ __align__(16) float g_xnhwc[BB*HH*WW*CIN];   // x in NHWC
__device__ __align__(16) float g_off9 [BB*HH*WW*9];     // raw conv1 out, channels 0..8
__device__ __align__(16) float g_wt1p [9*CIN*24];       // conv1 weights [tap][ci][6grp][4] (oc=3g+j, padded)
__device__ __align__(16) float g_wt2  [9*CIN*COUT];     // conv2 weights [k][ci][co]
__device__ float g_stats1[BB*9*2];                      // GN1 sum/sumsq per (b,group)
__device__ float g_stats2[BB*16*2];                     // GN2 sum/sumsq per (b,group)
__device__ float g_sc1[BB*9],  g_sh1[BB*9];             // GN1 per-channel scale/shift
__device__ float g_sc2[BB*COUT], g_sh2[BB*COUT];        // GN2 per-channel scale/shift

// ---------------- K: zero stats ----------------
__global__ void k_zero_stats() {
    int t = threadIdx.x;
    if (t < BB*9*2)  g_stats1[t] = 0.f;
    if (t < BB*16*2) g_stats2[t] = 0.f;
}

// ---------------- K: transpose x NCHW -> NHWC ----------------
__global__ void k_transpose_x(const float* __restrict__ x) {
    __shared__ float tile[32][33];
    int b  = blockIdx.z;
    int p0 = blockIdx.x * 32;
    int c0 = blockIdx.y * 32;
    int tx = threadIdx.x, ty = threadIdx.y;   // 32 x 8
    const float* xb = x + (size_t)b*CIN*HH*WW;
    #pragma unroll
    for (int i = 0; i < 32; i += 8)
        tile[ty+i][tx] = xb[(c0+ty+i)*(HH*WW) + p0 + tx];
    __syncthreads();
    float* ob = g_xnhwc + (size_t)b*HH*WW*CIN;
    #pragma unroll
    for (int i = 0; i < 32; i += 8)
        ob[(size_t)(p0+ty+i)*CIN + c0 + tx] = tile[tx][ty+i];
}

// ---------------- K: prep weights ----------------
__global__ void k_prep_w(const float* __restrict__ w_off, const float* __restrict__ w_dsc) {
    int t = blockIdx.x*blockDim.x + threadIdx.x;
    // g_wt1p: [tap][ci][g][4] with oc = 3g+j (j<3), pad j==3
    if (t < 9*CIN*24) {
        int tap = t / (CIN*24); int r = t % (CIN*24);
        int ci = r / 24; int gj = r % 24;
        int g = gj >> 2, j = gj & 3;
        int oc = g*3 + j;
        float v = 0.f;
        if (j < 3 && oc < OC1)
            v = w_off[oc*(CIN*9) + ci*9 + tap];        // w_off (18,64,3,3)
        g_wt1p[t] = v;
    }
    if (t < 9*CIN*COUT) {
        int k = t / (CIN*COUT); int r = t % (CIN*COUT);
        int ci = r / COUT; int co = r % COUT;
        g_wt2[t] = w_dsc[co*(CIN*9) + ci*9 + k];       // w_dsc (64,64,9,1) -> [k][ci][co]
    }
}

// ---------------- K: conv1 3x3 (64->18) + GN1 stats, GEMM-ified ----------------
// grid: B*H*2 (64-px half-rows), 96 threads: tx(0..15)->4px, ty(0..5)->3oc
// per ci: 2 LDS.128 (A, covers all 3 dx shifts) + 3x(1 broadcast LDS.128 W + 12 FMA)
__global__ __launch_bounds__(96) void k_conv1(const float* __restrict__ b_off) {
    __shared__ __align__(16) float xs [CIN*68];      // [ci][i], i=0..65 <-> w = w0+i-1
    __shared__ __align__(16) float wsp[3*CIN*24];    // [dx][ci][6grp][4]
    __shared__ float ssum[9], ssq[9];
    int t = threadIdx.x;
    int tx = t & 15, ty = t >> 4;
    int blk  = blockIdx.x;
    int half = blk & 1;
    int h    = (blk >> 1) & (HH-1);
    int b    = blk >> 8;
    int w0   = half * 64;
    if (t < 9) { ssum[t] = 0.f; ssq[t] = 0.f; }

    float acc[4][3];
    #pragma unroll
    for (int p=0;p<4;p++)
        #pragma unroll
        for (int j=0;j<3;j++) acc[p][j]=0.f;

    const float* xb = g_xnhwc + (size_t)b*(HH*WW*CIN);

    for (int dy = 0; dy < 3; dy++) {
        int y = h + dy - 1;
        __syncthreads();
        // stage one input row (66 positions x 64 ci), zero-padded
        for (int idx = t; idx < 66*16; idx += 96) {
            int pp = idx >> 4;       // i = pp, w = w0+pp-1
            int q  = idx & 15;
            int w  = w0 + pp - 1;
            float4 v = make_float4(0.f,0.f,0.f,0.f);
            if ((unsigned)y < HH && (unsigned)w < WW)
                v = *(const float4*)(xb + ((size_t)y*WW + w)*CIN + q*4);
            xs[(q*4+0)*68 + pp] = v.x;
            xs[(q*4+1)*68 + pp] = v.y;
            xs[(q*4+2)*68 + pp] = v.z;
            xs[(q*4+3)*68 + pp] = v.w;
        }
        // stage padded weights for this dy's 3 taps: contiguous [dx][ci][24]
        {
            const float4* wsrc = (const float4*)(g_wt1p + dy*3*CIN*24);
            float4* wdst = (float4*)wsp;
            for (int idx = t; idx < 3*CIN*6; idx += 96) wdst[idx] = wsrc[idx];
        }
        __syncthreads();
        #pragma unroll 2
        for (int ci = 0; ci < CIN; ci++) {
            // af[j] = input at i = tx*4 + j; output px p needs i = p + dx, p = tx*4+p_local
            const float4* ap = (const float4*)(xs + ci*68 + tx*4);
            float4 A0 = ap[0], A1 = ap[1];
            float af[8] = {A0.x,A0.y,A0.z,A0.w,A1.x,A1.y,A1.z,A1.w};
            #pragma unroll
            for (int dx = 0; dx < 3; dx++) {
                float4 wv = *(const float4*)(wsp + (dx*CIN + ci)*24 + ty*4);
                #pragma unroll
                for (int p = 0; p < 4; p++) {
                    float a = af[p+dx];
                    acc[p][0] += a*wv.x;
                    acc[p][1] += a*wv.y;
                    acc[p][2] += a*wv.z;
                }
            }
        }
    }
    __syncthreads();
    // epilogue: bias, store first 9 channels, GN1 stats (group = oc>>1)
    #pragma unroll
    for (int j = 0; j < 3; j++) {
        int oc = ty*3 + j;
        float bia = b_off[oc];
        float s = 0.f, sq = 0.f;
        #pragma unroll
        for (int p = 0; p < 4; p++) {
            float r = acc[p][j] + bia;
            s += r; sq += r*r;
            if (oc < 9)
                g_off9[(((size_t)b*HH + h)*WW + (w0 + tx*4 + p))*9 + oc] = r;
        }
        atomicAdd(&ssum[oc>>1], s);
        atomicAdd(&ssq [oc>>1], sq);
    }
    __syncthreads();
    if (t < 9) {
        atomicAdd(&g_stats1[(b*9 + t)*2 + 0], ssum[t]);
        atomicAdd(&g_stats1[(b*9 + t)*2 + 1], ssq[t]);
    }
}

// ---------------- K: finalize GN1 ----------------
__global__ void k_finalize1(const float* __restrict__ g_gn_off, const float* __restrict__ b_gn_off) {
    int t = threadIdx.x;
    if (t >= BB*9) return;
    int b = t / 9, c = t % 9, g = c >> 1;
    float N  = 2.f*HH*WW;
    float mu = g_stats1[(b*9+g)*2+0] / N;
    float var= g_stats1[(b*9+g)*2+1] / N - mu*mu;
    float inv= rsqrtf(var + 1e-5f);
    float sc = g_gn_off[c] * inv;
    g_sc1[t] = sc;
    g_sh1[t] = b_gn_off[c] - mu * sc;
}

// ---------------- K: main fused (offsets -> sample -> GEMM -> raw out + GN2 stats) ----------------
// grid: B*H*2 (64-px half-rows), 256 threads: 16x16, 4px x 4co micro-tile
// S stride 68 -> aligned broadcast LDS.128 for the A operand
__global__ __launch_bounds__(256) void k_main(const float* __restrict__ b_dsc, float* __restrict__ out) {
    __shared__ __align__(16) float S [CIN*68];    // samples [ci][px(68 pad)]
    __shared__ __align__(16) float Wc[CIN*COUT];  // weight chunk [ci][co]
    __shared__ int   cy0[9*64];
    __shared__ float cwy[9*64];
    __shared__ float sgrp[32];

    int t    = threadIdx.x;
    int blk  = blockIdx.x;
    int half = blk & 1;
    int h    = (blk >> 1) & (HH-1);
    int b    = blk >> 8;
    int w0   = half * 64;

    if (t < 32) sgrp[t] = 0.f;

    // ---- prologue: per-pixel offsets -> tanh -> cumsum -> coords ----
    if (t < 64) {
        int px = t;
        int w  = w0 + px;
        const float* op = g_off9 + (((size_t)b*HH + h)*WW + w)*9;
        float y[9];
        #pragma unroll
        for (int c = 0; c < 9; c++)
            y[c] = tanhf(op[c]*g_sc1[b*9+c] + g_sh1[b*9+c]);
        float o[9];
        o[4]=0.f;
        o[3]=y[3]; o[2]=y[2]+o[3]; o[1]=y[1]+o[2]; o[0]=y[0]+o[1];
        o[5]=y[5]; o[6]=o[5]+y[6]; o[7]=o[6]+y[7]; o[8]=o[7]+y[8];
        #pragma unroll
        for (int k = 0; k < 9; k++) {
            float yc  = fminf(fmaxf((float)h + o[k], 0.f), (float)(HH-1));
            float y0f = floorf(yc);
            cy0[k*64+px] = (int)y0f;
            cwy[k*64+px] = yc - y0f;
        }
    }

    int tx = t & 15, ty = t >> 4;
    float acc[4][4];
    #pragma unroll
    for (int i=0;i<4;i++)
        #pragma unroll
        for (int j=0;j<4;j++) acc[i][j]=0.f;

    int spx = t >> 2;            // sampling: one px per 4 threads
    int c4  = (t & 3) * 16;      // each thread: 16 channels
    const float* xb = g_xnhwc + (size_t)b*(HH*WW*CIN);

    for (int k = 0; k < 9; k++) {
        __syncthreads();
        // stage weight chunk [64ci][64co] (coalesced, pre-transposed)
        {
            const float4* wsrc = (const float4*)(g_wt2 + k*CIN*COUT);
            float4* wdst = (float4*)Wc;
            #pragma unroll
            for (int i = 0; i < 4; i++)
                wdst[t + i*256] = wsrc[t + i*256];
        }
        // build sample chunk: vertical 2-point lerp (x-coord is exact integer)
        {
            int w  = w0 + spx;
            int x0 = min(max(w + k - 4, 0), WW-1);
            int y0 = cy0[k*64 + spx];
            float wy = cwy[k*64 + spx];
            int y1 = min(y0 + 1, HH-1);
            const float* p0 = xb + ((size_t)y0*WW + x0)*CIN + c4;
            const float* p1 = xb + ((size_t)y1*WW + x0)*CIN + c4;
            #pragma unroll
            for (int q = 0; q < 4; q++) {
                float4 v0 = *(const float4*)(p0 + q*4);
                float4 v1 = *(const float4*)(p1 + q*4);
                int ci = c4 + q*4;
                S[(ci+0)*68 + spx] = v0.x + wy*(v1.x - v0.x);
                S[(ci+1)*68 + spx] = v0.y + wy*(v1.y - v0.y);
                S[(ci+2)*68 + spx] = v0.z + wy*(v1.z - v0.z);
                S[(ci+3)*68 + spx] = v0.w + wy*(v1.w - v0.w);
            }
        }
        __syncthreads();
        // SGEMM accumulate over this 64-ci chunk: 2 LDS.128 + 16 FFMA per ci
        #pragma unroll 2
        for (int ci = 0; ci < CIN; ci++) {
            float4 av = *(const float4*)(S + ci*68 + ty*4);     // broadcast
            float4 bb = *(const float4*)(Wc + ci*COUT + tx*4);
            acc[0][0]+=av.x*bb.x; acc[0][1]+=av.x*bb.y; acc[0][2]+=av.x*bb.z; acc[0][3]+=av.x*bb.w;
            acc[1][0]+=av.y*bb.x; acc[1][1]+=av.y*bb.y; acc[1][2]+=av.y*bb.z; acc[1][3]+=av.y*bb.w;
            acc[2][0]+=av.z*bb.x; acc[2][1]+=av.z*bb.y; acc[2][2]+=av.z*bb.z; acc[2][3]+=av.z*bb.w;
            acc[3][0]+=av.w*bb.x; acc[3][1]+=av.w*bb.y; acc[3][2]+=av.w*bb.z; acc[3][3]+=av.w*bb.w;
        }
    }
    __syncthreads();
    // epilogue: bias, raw store (NCHW), GN2 stats (co group == tx)
    float4 bia = *(const float4*)(b_dsc + tx*4);
    float s = 0.f, sq = 0.f;
    #pragma unroll
    for (int i = 0; i < 4; i++) {
        int w = w0 + ty*4 + i;
        float r0 = acc[i][0] + bia.x;
        float r1 = acc[i][1] + bia.y;
        float r2 = acc[i][2] + bia.z;
        float r3 = acc[i][3] + bia.w;
        out[(((size_t)b*COUT + tx*4+0)*HH + h)*WW + w] = r0;
        out[(((size_t)b*COUT + tx*4+1)*HH + h)*WW + w] = r1;
        out[(((size_t)b*COUT + tx*4+2)*HH + h)*WW + w] = r2;
        out[(((size_t)b*COUT + tx*4+3)*HH + h)*WW + w] = r3;
        s  += r0+r1+r2+r3;
        sq += r0*r0 + r1*r1 + r2*r2 + r3*r3;
    }
    atomicAdd(&sgrp[tx*2+0], s);
    atomicAdd(&sgrp[tx*2+1], sq);
    __syncthreads();
    if (t < 32) atomicAdd(&g_stats2[b*32 + t], sgrp[t]);
}

// ---------------- K: finalize GN2 ----------------
__global__ void k_finalize2(const float* __restrict__ g_gn, const float* __restrict__ b_gn) {
    int t = threadIdx.x;
    if (t >= BB*COUT) return;
    int b = t >> 6, co = t & 63, g = co >> 2;
    float N  = 4.f*HH*WW;
    float mu = g_stats2[(b*16+g)*2+0] / N;
    float var= g_stats2[(b*16+g)*2+1] / N - mu*mu;
    float inv= rsqrtf(var + 1e-5f);
    float sc = g_gn[co] * inv;
    g_sc2[t] = sc;
    g_sh2[t] = b_gn[co] - mu * sc;
}

// ---------------- K: normalize + relu in place ----------------
__global__ void k_norm_relu(float* __restrict__ out) {
    int idx = blockIdx.x*blockDim.x + threadIdx.x;   // float4 index
    int e  = idx << 2;
    int bc = e >> 14;                                 // b*64+co
    float sc = g_sc2[bc], sh = g_sh2[bc];
    float4 v = ((float4*)out)[idx];
    v.x = fmaxf(v.x*sc + sh, 0.f);
    v.y = fmaxf(v.y*sc + sh, 0.f);
    v.z = fmaxf(v.z*sc + sh, 0.f);
    v.w = fmaxf(v.w*sc + sh, 0.f);
    ((float4*)out)[idx] = v;
}

// ---------------- launch ----------------
extern "C" void kernel_launch(void* const* d_in, const int* in_sizes, int n_in,
                              void* d_out, int out_size) {
    const float* x        = (const float*)d_in[0];
    const float* w_off    = (const float*)d_in[1];
    const float* b_off    = (const float*)d_in[2];
    const float* g_gn_off = (const float*)d_in[3];
    const float* b_gn_off = (const float*)d_in[4];
    const float* w_dsc    = (const float*)d_in[5];
    const float* b_dsc    = (const float*)d_in[6];
    const float* g_gn     = (const float*)d_in[7];
    const float* b_gn     = (const float*)d_in[8];
    float* out = (float*)d_out;

    k_zero_stats<<<1,128>>>();
    k_transpose_x<<<dim3(512,2,4), dim3(32,8)>>>(x);
    k_prep_w<<<144,256>>>(w_off, w_dsc);
    k_conv1<<<BB*HH*2, 96>>>(b_off);
    k_finalize1<<<1,64>>>(g_gn_off, b_gn_off);
    k_main<<<BB*HH*2, 256>>>(b_dsc, out);
    k_finalize2<<<1,256>>>(g_gn, b_gn);
    k_norm_relu<<<4096,256>>>(out);
}